// round 1
// baseline (speedup 1.0000x reference)
#include <cuda_runtime.h>

// Problem constants
#define BB 10
#define CC 3
#define HH 50
#define WW 101
#define KK 4096
#define K1 4097

#define GRID_N (BB*CC*HH*WW)          // 151500

// conv1: in [10,3,50,101] -> out [10,32,25,51]
#define C1_CO 32
#define C1_OH 25
#define C1_OW 51
#define C1_N  (BB*C1_CO*C1_OH*C1_OW)  // 408000

// pool1: 3x3 s2 -> [10,32,12,25]
#define P1_OH 12
#define P1_OW 25
#define P1_N  (BB*C1_CO*P1_OH*P1_OW)  // 96000

// conv2: 5x5 s1 p2 -> [10,64,12,25]
#define C2_CO 64
#define C2_N  (BB*C2_CO*P1_OH*P1_OW)  // 192000

// pool2: 2x2 s2 -> [10,64,6,12]
#define P2_OH 6
#define P2_OW 12
#define P2_N  (BB*C2_CO*P2_OH*P2_OW)  // 46080

// conv3: 3x3 s1 p1 -> [10,128,6,12]
#define C3_CO 128
#define C3_N  (BB*C3_CO*P2_OH*P2_OW)  // 92160

// Scratch buffers (allocation-free: __device__ globals)
__device__ int   g_order[GRID_N];
__device__ float g_grid[GRID_N];
__device__ float g_c1[C1_N];
__device__ float g_p1[P1_N];
__device__ float g_c2[C2_N];
__device__ float g_p2[P2_N];
__device__ float g_c3[C3_N];
__device__ float g_gap[BB*C3_CO];

// ---------------------------------------------------------------------------
// 1. init order array to -1
__global__ void init_order() {
    int t = blockIdx.x * blockDim.x + threadIdx.x;
    if (t < GRID_N) g_order[t] = -1;
}

// 2. scatter: one thread per point (incl. the implicit base point at k==0),
//    10 atomicMax writes with the sequential write-order as the value.
__global__ void scatter_points(const int* __restrict__ x) {
    int t = blockIdx.x * blockDim.x + threadIdx.x;
    const int total = BB * CC * K1;
    if (t >= total) return;
    int k = t % K1;
    int c = (t / K1) % CC;
    int b = t / (K1 * CC);
    int col, row;
    if (k == 0) { col = 50; row = 48; }
    else {
        int base = (((b * CC + c) * KK) + (k - 1)) * 2;
        col = x[base + 0];
        row = x[base + 1];
    }
    const int drs[10] = {-1,-1,-1, 0,0,0, 1,1,1, 0};
    const int dcs[10] = {-1, 0, 1,-1,0,1,-1,0,1, 0};
    int slice = (b * CC + c) * HH;
    int ord0 = k * 10;
#pragma unroll
    for (int w = 0; w < 10; w++) {
        int cell = (slice + row + drs[w]) * WW + (col + dcs[w]);
        atomicMax(&g_order[cell], ord0 + w);
    }
}

// 3. order -> float grid
__global__ void convert_grid() {
    int t = blockIdx.x * blockDim.x + threadIdx.x;
    if (t >= GRID_N) return;
    int o = g_order[t];
    float v = 0.0f;
    if (o >= 0) v = ((o % 10) == 9) ? 1.0f : 0.5f;
    g_grid[t] = v;
}

// 4. conv1 7x7 s2 p3 + relu (direct)
__global__ void conv1_relu(const float* __restrict__ w1, const float* __restrict__ b1) {
    int t = blockIdx.x * blockDim.x + threadIdx.x;
    if (t >= C1_N) return;
    int ow = t % C1_OW;
    int oh = (t / C1_OW) % C1_OH;
    int co = (t / (C1_OW * C1_OH)) % C1_CO;
    int b  = t / (C1_OW * C1_OH * C1_CO);
    float s = b1[co];
#pragma unroll
    for (int ci = 0; ci < CC; ci++) {
        const float* in = g_grid + (b * CC + ci) * HH * WW;
        const float* wt = w1 + (co * CC + ci) * 49;
#pragma unroll
        for (int kh = 0; kh < 7; kh++) {
            int ih = oh * 2 - 3 + kh;
            if (ih < 0 || ih >= HH) continue;
#pragma unroll
            for (int kw = 0; kw < 7; kw++) {
                int iw = ow * 2 - 3 + kw;
                if (iw < 0 || iw >= WW) continue;
                s += in[ih * WW + iw] * wt[kh * 7 + kw];
            }
        }
    }
    g_c1[t] = fmaxf(s, 0.0f);
}

// 5. maxpool 3x3 s2: [25,51] -> [12,25]
__global__ void pool1() {
    int t = blockIdx.x * blockDim.x + threadIdx.x;
    if (t >= P1_N) return;
    int ow = t % P1_OW;
    int oh = (t / P1_OW) % P1_OH;
    int bc = t / (P1_OW * P1_OH);  // b*32+co
    const float* in = g_c1 + bc * (C1_OH * C1_OW);
    float m = -1e30f;
#pragma unroll
    for (int i = 0; i < 3; i++)
#pragma unroll
        for (int j = 0; j < 3; j++) {
            float v = in[(oh * 2 + i) * C1_OW + (ow * 2 + j)];
            m = fmaxf(m, v);
        }
    g_p1[t] = m;
}

// 6. conv2 5x5 s1 p2 + relu. Block = (b, co); 300 threads (12x25).
//    Full input slice [32,12,25] and weights [32,5,5] in shared memory.
__global__ void conv2_relu(const float* __restrict__ w2, const float* __restrict__ b2) {
    __shared__ float s_in[C1_CO * P1_OH * P1_OW]; // 9600 floats
    __shared__ float s_w[C1_CO * 25];             // 800 floats
    int b  = blockIdx.x / C2_CO;
    int co = blockIdx.x % C2_CO;
    for (int i = threadIdx.x; i < C1_CO * P1_OH * P1_OW; i += blockDim.x)
        s_in[i] = g_p1[b * (C1_CO * P1_OH * P1_OW) + i];
    for (int i = threadIdx.x; i < C1_CO * 25; i += blockDim.x)
        s_w[i] = w2[co * (C1_CO * 25) + i];
    __syncthreads();
    int oh = threadIdx.x / P1_OW;
    int ow = threadIdx.x % P1_OW;
    float s = b2[co];
#pragma unroll 4
    for (int ci = 0; ci < C1_CO; ci++) {
        const float* in = s_in + ci * (P1_OH * P1_OW);
        const float* wt = s_w + ci * 25;
#pragma unroll
        for (int kh = 0; kh < 5; kh++) {
            int ih = oh - 2 + kh;
            if (ih < 0 || ih >= P1_OH) continue;
#pragma unroll
            for (int kw = 0; kw < 5; kw++) {
                int iw = ow - 2 + kw;
                if (iw < 0 || iw >= P1_OW) continue;
                s += in[ih * P1_OW + iw] * wt[kh * 5 + kw];
            }
        }
    }
    g_c2[(b * C2_CO + co) * (P1_OH * P1_OW) + threadIdx.x] = fmaxf(s, 0.0f);
}

// 7. maxpool 2x2 s2: [12,25] -> [6,12]
__global__ void pool2() {
    int t = blockIdx.x * blockDim.x + threadIdx.x;
    if (t >= P2_N) return;
    int ow = t % P2_OW;
    int oh = (t / P2_OW) % P2_OH;
    int bc = t / (P2_OW * P2_OH);
    const float* in = g_c2 + bc * (P1_OH * P1_OW);
    float m = fmaxf(fmaxf(in[(oh*2)*P1_OW + ow*2],     in[(oh*2)*P1_OW + ow*2+1]),
                    fmaxf(in[(oh*2+1)*P1_OW + ow*2],   in[(oh*2+1)*P1_OW + ow*2+1]));
    g_p2[t] = m;
}

// 8. conv3 3x3 s1 p1 + relu. Block = (b, group of 8 co); 576 threads.
__global__ void conv3_relu(const float* __restrict__ w3, const float* __restrict__ b3) {
    __shared__ float s_in[C2_CO * P2_OH * P2_OW];  // 4608 floats
    __shared__ float s_w[8 * C2_CO * 9];           // 4608 floats
    int b   = blockIdx.x / 16;
    int cog = blockIdx.x % 16;
    for (int i = threadIdx.x; i < C2_CO * P2_OH * P2_OW; i += blockDim.x)
        s_in[i] = g_p2[b * (C2_CO * P2_OH * P2_OW) + i];
    for (int i = threadIdx.x; i < 8 * C2_CO * 9; i += blockDim.x)
        s_w[i] = w3[cog * (8 * C2_CO * 9) + i];
    __syncthreads();
    int col = threadIdx.x / 72;      // 0..7 within co group
    int pos = threadIdx.x % 72;
    int oh = pos / P2_OW;
    int ow = pos % P2_OW;
    int co = cog * 8 + col;
    float s = b3[co];
    for (int ci = 0; ci < C2_CO; ci++) {
        const float* in = s_in + ci * (P2_OH * P2_OW);
        const float* wt = s_w + (col * C2_CO + ci) * 9;
#pragma unroll
        for (int kh = 0; kh < 3; kh++) {
            int ih = oh - 1 + kh;
            if (ih < 0 || ih >= P2_OH) continue;
#pragma unroll
            for (int kw = 0; kw < 3; kw++) {
                int iw = ow - 1 + kw;
                if (iw < 0 || iw >= P2_OW) continue;
                s += in[ih * P2_OW + iw] * wt[kh * 3 + kw];
            }
        }
    }
    g_c3[(b * C3_CO + co) * 72 + pos] = fmaxf(s, 0.0f);
}

// 9. maxpool 2x2 s2 ([6,12]->[3,6]) fused with global average (mean over 18)
__global__ void pool3_gap() {
    int t = blockIdx.x * blockDim.x + threadIdx.x;
    if (t >= BB * C3_CO) return;
    const float* in = g_c3 + t * 72;
    float acc = 0.0f;
#pragma unroll
    for (int ph = 0; ph < 3; ph++)
#pragma unroll
        for (int pw = 0; pw < 6; pw++) {
            float m = fmaxf(fmaxf(in[(ph*2)*12 + pw*2],   in[(ph*2)*12 + pw*2+1]),
                            fmaxf(in[(ph*2+1)*12 + pw*2], in[(ph*2+1)*12 + pw*2+1]));
            acc += m;
        }
    g_gap[t] = acc * (1.0f / 18.0f);
}

// 10. fc1(128->128)+relu then fc2(128->5). One block per batch row.
__global__ void fc_fused(const float* __restrict__ wl1, const float* __restrict__ bl1,
                         const float* __restrict__ wl2, const float* __restrict__ bl2,
                         float* __restrict__ out) {
    __shared__ float s_g[128];
    __shared__ float s_h[128];
    int b = blockIdx.x;
    int t = threadIdx.x;
    s_g[t] = g_gap[b * 128 + t];
    __syncthreads();
    float s = bl1[t];
    const float* wr = wl1 + t * 128;
#pragma unroll 8
    for (int i = 0; i < 128; i++) s += s_g[i] * wr[i];
    s_h[t] = fmaxf(s, 0.0f);
    __syncthreads();
    if (t < 5) {
        float o = bl2[t];
        const float* wr2 = wl2 + t * 128;
#pragma unroll 8
        for (int i = 0; i < 128; i++) o += s_h[i] * wr2[i];
        out[b * 5 + t] = o;
    }
}

extern "C" void kernel_launch(void* const* d_in, const int* in_sizes, int n_in,
                              void* d_out, int out_size) {
    const int*   x   = (const int*)  d_in[0];
    const float* w1  = (const float*)d_in[1];
    const float* b1  = (const float*)d_in[2];
    const float* w2  = (const float*)d_in[3];
    const float* b2  = (const float*)d_in[4];
    const float* w3  = (const float*)d_in[5];
    const float* b3  = (const float*)d_in[6];
    const float* wl1 = (const float*)d_in[7];
    const float* bl1 = (const float*)d_in[8];
    const float* wl2 = (const float*)d_in[9];
    const float* bl2 = (const float*)d_in[10];
    float* out = (float*)d_out;

    init_order<<<(GRID_N + 255) / 256, 256>>>();
    scatter_points<<<(BB * CC * K1 + 255) / 256, 256>>>(x);
    convert_grid<<<(GRID_N + 255) / 256, 256>>>();
    conv1_relu<<<(C1_N + 255) / 256, 256>>>(w1, b1);
    pool1<<<(P1_N + 255) / 256, 256>>>();
    conv2_relu<<<BB * C2_CO, 300>>>(w2, b2);
    pool2<<<(P2_N + 255) / 256, 256>>>();
    conv3_relu<<<BB * 16, 576>>>(w3, b3);
    pool3_gap<<<(BB * C3_CO + 255) / 256, 256>>>();
    fc_fused<<<BB, 128>>>(wl1, bl1, wl2, bl2, out);
}

// round 2
// speedup vs baseline: 1.5429x; 1.5429x over previous
#include <cuda_runtime.h>

#define BB 10
#define CC 3
#define HH 50
#define WW 101
#define KK 4096

// Padded grid for conv1 (pad=3): [30][56][107]
#define HP 56
#define WP 107
#define GRIDP_N (BB*CC*HP*WP)

// pool1 out, padded for conv2 (pad=2): [10][32][16][29]
#define P1_PAD_N (BB*32*16*29)
// pool2 out, padded for conv3 (pad=1): [10][64][8][14]
#define P2_PAD_N (BB*64*8*14)

__device__ float g_gridp[GRIDP_N];
__device__ float g_p1[P1_PAD_N];
__device__ float g_p2[P2_PAD_N];
__device__ float g_gap[BB*128];

// ---------------------------------------------------------------------------
// 1. Build grid: smem atomicMax scatter + write padded float grid.
//    One block per (b,c) slice. Order value = k*10 + w; center (w=9) always
//    dominates the duplicate (0,0) write at w=4, so w=4 is skipped.
__global__ void build_grid(const int* __restrict__ x) {
    __shared__ int s_ord[HH*WW];   // 5050 ints
    int bc = blockIdx.x;           // b*3 + c
    for (int i = threadIdx.x; i < HH*WW; i += blockDim.x) s_ord[i] = -1;
    __syncthreads();
    const int2* xp = (const int2*)x;
    for (int k = threadIdx.x; k < KK + 1; k += blockDim.x) {
        int col, row;
        if (k == 0) { col = 50; row = 48; }
        else { int2 p = xp[bc*KK + k - 1]; col = p.x; row = p.y; }
        int base = row * WW + col;
        int o = k * 10;
        atomicMax(&s_ord[base-WW-1], o+0);
        atomicMax(&s_ord[base-WW  ], o+1);
        atomicMax(&s_ord[base-WW+1], o+2);
        atomicMax(&s_ord[base-1   ], o+3);
        atomicMax(&s_ord[base+1   ], o+5);
        atomicMax(&s_ord[base+WW-1], o+6);
        atomicMax(&s_ord[base+WW  ], o+7);
        atomicMax(&s_ord[base+WW+1], o+8);
        atomicMax(&s_ord[base     ], o+9);
    }
    __syncthreads();
    float* gp = g_gridp + bc * HP * WP;
    for (int q = threadIdx.x; q < HP*WP; q += blockDim.x) {
        int r = q / WP, cl = q % WP;
        float v = 0.f;
        if (r >= 3 && r < 3+HH && cl >= 3 && cl < 3+WW) {
            int o = s_ord[(r-3)*WW + (cl-3)];
            if (o >= 0) v = ((o % 10) == 9) ? 1.0f : 0.5f;
        }
        gp[q] = v;
    }
}

// ---------------------------------------------------------------------------
// 2. conv1 (7x7 s2 p3, 3->32) + relu + maxpool 3x3 s2, write padded [16][29].
//    Block = (b, co-pair). Conv out 25x51 per co kept in smem.
__global__ void conv1_pool1(const float* __restrict__ w1, const float* __restrict__ b1) {
    __shared__ float s_w[2][147];
    __shared__ float s_c[2][25*51];
    int b = blockIdx.x / 16, cp = blockIdx.x % 16;
    int co0 = cp * 2;
    for (int i = threadIdx.x; i < 294; i += 256) {
        int u = i / 147, j = i % 147;
        s_w[u][j] = w1[(co0 + u) * 147 + j];
    }
    __syncthreads();
    const float* in = g_gridp + b * 3 * HP * WP;
    float bias0 = b1[co0], bias1 = b1[co0+1];
    for (int p = threadIdx.x; p < 25*51; p += 256) {
        int oh = p / 51, ow = p % 51;
        const float* ibase = in + (oh*2) * WP + ow*2;
        float a0 = bias0, a1 = bias1;
#pragma unroll
        for (int ci = 0; ci < 3; ci++) {
#pragma unroll
            for (int kh = 0; kh < 7; kh++) {
                const float* r = ibase + ci * (HP*WP) + kh * WP;
#pragma unroll
                for (int kw = 0; kw < 7; kw++) {
                    float v = r[kw];
                    int wi = ci*49 + kh*7 + kw;
                    a0 += v * s_w[0][wi];
                    a1 += v * s_w[1][wi];
                }
            }
        }
        s_c[0][p] = fmaxf(a0, 0.f);
        s_c[1][p] = fmaxf(a1, 0.f);
    }
    __syncthreads();
    // pool 3x3 s2 -> 12x25, write padded [16][29] (pad=2 borders zero)
    for (int q = threadIdx.x; q < 2*16*29; q += 256) {
        int u = q / 464, rc = q % 464, r = rc / 29, cl = rc % 29;
        float v = 0.f;
        if (r >= 2 && r < 14 && cl >= 2 && cl < 27) {
            const float* c = s_c[u] + ((r-2)*2) * 51 + (cl-2)*2;
            float m = fmaxf(fmaxf(c[0], c[1]), c[2]);
            m = fmaxf(m, fmaxf(fmaxf(c[51], c[52]), c[53]));
            m = fmaxf(m, fmaxf(fmaxf(c[102], c[103]), c[104]));
            v = m;
        }
        g_p1[((b*32 + co0 + u) * 16 + r) * 29 + cl] = v;
    }
}

// ---------------------------------------------------------------------------
// 3. conv2 (5x5 s1 p2, 32->64) + relu + maxpool 2x2 s2, write padded [8][14].
//    Block = (b, group of 4 co). Thread: T=5 ow, U=2 co. Input padded in smem.
__global__ void conv2_pool2(const float* __restrict__ w2, const float* __restrict__ b2) {
    extern __shared__ float sm[];
    float* s_in = sm;            // 32*16*29 = 14848
    float* s_w  = sm + 14848;    // 4*800 = 3200
    float* s_c  = sm + 18048;    // 4*300 = 1200
    int b = blockIdx.x / 16, cog = blockIdx.x % 16;
    {
        const float4* src = (const float4*)(g_p1 + b * 14848);
        float4* dst = (float4*)s_in;
        for (int i = threadIdx.x; i < 3712; i += 128) dst[i] = src[i];
        const float4* wsrc = (const float4*)(w2 + cog * 3200);
        float4* wdst = (float4*)s_w;
        for (int i = threadIdx.x; i < 800; i += 128) wdst[i] = wsrc[i];
    }
    __syncthreads();
    if (threadIdx.x < 120) {
        int u2 = threadIdx.x / 60, pos = threadIdx.x % 60;
        int oh = pos / 5, ow0 = (pos % 5) * 5;
        int co0 = cog*4 + u2*2;
        float acc0[5], acc1[5];
        float bb0 = b2[co0], bb1 = b2[co0+1];
#pragma unroll
        for (int t = 0; t < 5; t++) { acc0[t] = bb0; acc1[t] = bb1; }
        const float* wp0 = s_w + (u2*2) * 800;
        const float* wp1 = wp0 + 800;
        for (int ci = 0; ci < 32; ci++) {
            const float* ip = s_in + ci*464 + oh*29 + ow0;
            const float* w0 = wp0 + ci*25;
            const float* w1 = wp1 + ci*25;
#pragma unroll
            for (int kh = 0; kh < 5; kh++) {
                const float* row = ip + kh*29;
                float iv[9];
#pragma unroll
                for (int m = 0; m < 9; m++) iv[m] = row[m];
#pragma unroll
                for (int kw = 0; kw < 5; kw++) {
                    float a = w0[kh*5+kw], c = w1[kh*5+kw];
#pragma unroll
                    for (int t = 0; t < 5; t++) {
                        acc0[t] += iv[kw+t] * a;
                        acc1[t] += iv[kw+t] * c;
                    }
                }
            }
        }
#pragma unroll
        for (int t = 0; t < 5; t++) {
            s_c[(u2*2  )*300 + oh*25 + ow0 + t] = fmaxf(acc0[t], 0.f);
            s_c[(u2*2+1)*300 + oh*25 + ow0 + t] = fmaxf(acc1[t], 0.f);
        }
    }
    __syncthreads();
    // pool 2x2 s2 -> 6x12, write padded [8][14] (pad=1)
    for (int q = threadIdx.x; q < 4*8*14; q += 128) {
        int u = q / 112, rc = q % 112, r = rc / 14, cl = rc % 14;
        float v = 0.f;
        if (r >= 1 && r < 7 && cl >= 1 && cl < 13) {
            const float* c = s_c + u*300 + ((r-1)*2)*25 + (cl-1)*2;
            v = fmaxf(fmaxf(c[0], c[1]), fmaxf(c[25], c[26]));
        }
        g_p2[((b*64 + cog*4 + u) * 8 + r) * 14 + cl] = v;
    }
}

// ---------------------------------------------------------------------------
// 4. conv3 (3x3 s1 p1, 64->128) + relu + maxpool 2x2 + global-avg.
//    Block = (b, group of 8 co). Thread: T=2 ow, U=2 co.
__global__ void conv3_gap(const float* __restrict__ w3, const float* __restrict__ b3) {
    extern __shared__ float sm[];
    float* s_in = sm;            // 64*8*14 = 7168
    float* s_w  = sm + 7168;     // 8*576 = 4608
    float* s_c  = sm + 11776;    // 8*72 = 576
    float* s_p  = sm + 12352;    // 144
    int b = blockIdx.x / 16, cog = blockIdx.x % 16;
    {
        const float4* src = (const float4*)(g_p2 + b * 7168);
        float4* dst = (float4*)s_in;
        for (int i = threadIdx.x; i < 1792; i += 160) dst[i] = src[i];
        const float4* wsrc = (const float4*)(w3 + cog * 4608);
        float4* wdst = (float4*)s_w;
        for (int i = threadIdx.x; i < 1152; i += 160) wdst[i] = wsrc[i];
    }
    __syncthreads();
    if (threadIdx.x < 144) {
        int u2 = threadIdx.x / 36, pos = threadIdx.x % 36;
        int oh = pos / 6, ow0 = (pos % 6) * 2;
        int co0 = cog*8 + u2*2;
        float acc0[2], acc1[2];
        acc0[0] = acc0[1] = b3[co0];
        acc1[0] = acc1[1] = b3[co0+1];
        const float* wp0 = s_w + (u2*2) * 576;
        const float* wp1 = wp0 + 576;
        for (int ci = 0; ci < 64; ci++) {
            const float* ip = s_in + ci*112 + oh*14 + ow0;
            const float* w0 = wp0 + ci*9;
            const float* w1 = wp1 + ci*9;
#pragma unroll
            for (int kh = 0; kh < 3; kh++) {
                const float* row = ip + kh*14;
                float iv[4];
#pragma unroll
                for (int m = 0; m < 4; m++) iv[m] = row[m];
#pragma unroll
                for (int kw = 0; kw < 3; kw++) {
                    float a = w0[kh*3+kw], c = w1[kh*3+kw];
                    acc0[0] += iv[kw]   * a;
                    acc0[1] += iv[kw+1] * a;
                    acc1[0] += iv[kw]   * c;
                    acc1[1] += iv[kw+1] * c;
                }
            }
        }
        s_c[(u2*2  )*72 + oh*12 + ow0    ] = fmaxf(acc0[0], 0.f);
        s_c[(u2*2  )*72 + oh*12 + ow0 + 1] = fmaxf(acc0[1], 0.f);
        s_c[(u2*2+1)*72 + oh*12 + ow0    ] = fmaxf(acc1[0], 0.f);
        s_c[(u2*2+1)*72 + oh*12 + ow0 + 1] = fmaxf(acc1[1], 0.f);
    }
    __syncthreads();
    if (threadIdx.x < 144) {
        int col = threadIdx.x / 18, cell = threadIdx.x % 18;
        int ph = cell / 6, pw = cell % 6;
        const float* c = s_c + col*72 + (ph*2)*12 + pw*2;
        s_p[threadIdx.x] = fmaxf(fmaxf(c[0], c[1]), fmaxf(c[12], c[13]));
    }
    __syncthreads();
    if (threadIdx.x < 8) {
        float s = 0.f;
#pragma unroll
        for (int i = 0; i < 18; i++) s += s_p[threadIdx.x*18 + i];
        g_gap[b*128 + cog*8 + threadIdx.x] = s * (1.0f/18.0f);
    }
}

// ---------------------------------------------------------------------------
// 5. fc1(128->128)+relu, fc2(128->5). One block per batch row.
__global__ void fc_fused(const float* __restrict__ wl1, const float* __restrict__ bl1,
                         const float* __restrict__ wl2, const float* __restrict__ bl2,
                         float* __restrict__ out) {
    __shared__ float s_g[128];
    __shared__ float s_h[128];
    int b = blockIdx.x;
    int t = threadIdx.x;
    s_g[t] = g_gap[b*128 + t];
    __syncthreads();
    float s = bl1[t];
    const float* wr = wl1 + t*128;
#pragma unroll 8
    for (int i = 0; i < 128; i++) s += s_g[i] * wr[i];
    s_h[t] = fmaxf(s, 0.f);
    __syncthreads();
    if (t < 5) {
        float o = bl2[t];
        const float* wr2 = wl2 + t*128;
#pragma unroll 8
        for (int i = 0; i < 128; i++) o += s_h[i] * wr2[i];
        out[b*5 + t] = o;
    }
}

extern "C" void kernel_launch(void* const* d_in, const int* in_sizes, int n_in,
                              void* d_out, int out_size) {
    const int*   x   = (const int*)  d_in[0];
    const float* w1  = (const float*)d_in[1];
    const float* b1  = (const float*)d_in[2];
    const float* w2  = (const float*)d_in[3];
    const float* b2  = (const float*)d_in[4];
    const float* w3  = (const float*)d_in[5];
    const float* b3  = (const float*)d_in[6];
    const float* wl1 = (const float*)d_in[7];
    const float* bl1 = (const float*)d_in[8];
    const float* wl2 = (const float*)d_in[9];
    const float* bl2 = (const float*)d_in[10];
    float* out = (float*)d_out;

    const int smem2 = (14848 + 3200 + 1200) * 4;          // 76992 B
    const int smem3 = (7168 + 4608 + 576 + 144) * 4;      // 49984 B
    cudaFuncSetAttribute(conv2_pool2, cudaFuncAttributeMaxDynamicSharedMemorySize, smem2);
    cudaFuncSetAttribute(conv3_gap,   cudaFuncAttributeMaxDynamicSharedMemorySize, smem3);

    build_grid <<<BB*CC, 512>>>(x);
    conv1_pool1<<<BB*16, 256>>>(w1, b1);
    conv2_pool2<<<BB*16, 128, smem2>>>(w2, b2);
    conv3_gap  <<<BB*16, 160, smem3>>>(w3, b3);
    fc_fused   <<<BB, 128>>>(wl1, bl1, wl2, bl2, out);
}

// round 3
// speedup vs baseline: 2.2416x; 1.4529x over previous
#include <cuda_runtime.h>

#define BB 10
#define CC 3
#define HH 50
#define WW 101
#define KK 4096

// Padded grid for conv1 (pad=3): [30][56][107]
#define HP 56
#define WP 107
#define GRIDP_N (BB*CC*HP*WP)
#define SLICE (HP*WP)                 // 5992

// pool1 out, padded for conv2 (pad=2): [10][32][16][29]
#define P1_PAD_N (BB*32*16*29)
// pool2 out, padded for conv3 (pad=1): [10][64][8][14]
#define P2_PAD_N (BB*64*8*14)

__device__ float g_gridp[GRIDP_N];
__device__ float g_p1[P1_PAD_N];
__device__ float g_p2[P2_PAD_N];
__device__ float g_gap[BB*128];

// packed fp32x2 FMA (Blackwell, PTX 8.7): acc += a * b elementwise, exact fp32
__device__ __forceinline__ void ffma2(float2& acc, float2 a, float2 b) {
    union { float2 f; unsigned long long u; } ua, ub, uc;
    ua.f = a; ub.f = b; uc.f = acc;
    asm("fma.rn.f32x2 %0, %1, %2, %0;" : "+l"(uc.u) : "l"(ua.u), "l"(ub.u));
    acc = uc.f;
}

// ---------------------------------------------------------------------------
// 1. Build grid: smem atomicMax scatter, write padded float grid.
__global__ void build_grid(const int* __restrict__ x) {
    __shared__ int s_ord[HH*WW];
    int bc = blockIdx.x;
    for (int i = threadIdx.x; i < HH*WW; i += blockDim.x) s_ord[i] = -1;
    __syncthreads();
    const int2* xp = (const int2*)x;
    for (int k = threadIdx.x; k < KK + 1; k += blockDim.x) {
        int col, row;
        if (k == 0) { col = 50; row = 48; }
        else { int2 p = xp[bc*KK + k - 1]; col = p.x; row = p.y; }
        int base = row * WW + col;
        int o = k * 10;
        atomicMax(&s_ord[base-WW-1], o+0);
        atomicMax(&s_ord[base-WW  ], o+1);
        atomicMax(&s_ord[base-WW+1], o+2);
        atomicMax(&s_ord[base-1   ], o+3);
        atomicMax(&s_ord[base+1   ], o+5);
        atomicMax(&s_ord[base+WW-1], o+6);
        atomicMax(&s_ord[base+WW  ], o+7);
        atomicMax(&s_ord[base+WW+1], o+8);
        atomicMax(&s_ord[base     ], o+9);
    }
    __syncthreads();
    float* gp = g_gridp + bc * SLICE;
    for (int q = threadIdx.x; q < SLICE; q += blockDim.x) {
        int r = q / WP, cl = q % WP;
        float v = 0.f;
        if (r >= 3 && r < 3+HH && cl >= 3 && cl < 3+WW) {
            int o = s_ord[(r-3)*WW + (cl-3)];
            if (o >= 0) v = ((o % 10) == 9) ? 1.0f : 0.5f;
        }
        gp[q] = v;
    }
}

// ---------------------------------------------------------------------------
// 2. conv1 7x7 s2 (3->32) + relu + pool 3x3 s2 -> padded [16][29].
//    Block=(b, co-pair): 160 blocks x 448 threads. Thread: 3 ow x 2 co (f32x2).
__global__ void conv1_pool1(const float* __restrict__ w1, const float* __restrict__ b1) {
    extern __shared__ float sm[];
    float* s_in = sm;              // 3*56*107 = 17976
    float* s_w  = sm + 17976;      // 147*2 = 294 (co-interleaved)
    float* s_c  = sm + 18272;      // 2*25*51 = 2550
    int b = blockIdx.x >> 4, cp = blockIdx.x & 15;
    int co0 = cp * 2;
    {
        const float4* src = (const float4*)(g_gridp + b * 3 * SLICE);
        float4* dst = (float4*)s_in;
        for (int i = threadIdx.x; i < 3*SLICE/4; i += 448) dst[i] = src[i];
        for (int i = threadIdx.x; i < 294; i += 448) {
            int j = i >> 1, u = i & 1;
            s_w[i] = w1[(co0 + u) * 147 + j];
        }
    }
    __syncthreads();
    int p = threadIdx.x;
    if (p < 425) {
        int oh = p / 17, ow0 = (p % 17) * 3;
        float2 bias = make_float2(b1[co0], b1[co0+1]);
        float2 acc[3] = {bias, bias, bias};
        const float2* wv = (const float2*)s_w;
#pragma unroll
        for (int ci = 0; ci < 3; ci++) {
#pragma unroll
            for (int kh = 0; kh < 7; kh++) {
                const float* row = s_in + ci * SLICE + (oh*2 + kh) * WP + ow0*2;
                float iv[11];
#pragma unroll
                for (int m = 0; m < 11; m++) iv[m] = row[m];
#pragma unroll
                for (int kw = 0; kw < 7; kw++) {
                    float2 w = wv[ci*49 + kh*7 + kw];
                    ffma2(acc[0], make_float2(iv[kw  ], iv[kw  ]), w);
                    ffma2(acc[1], make_float2(iv[kw+2], iv[kw+2]), w);
                    ffma2(acc[2], make_float2(iv[kw+4], iv[kw+4]), w);
                }
            }
        }
#pragma unroll
        for (int t = 0; t < 3; t++) {
            s_c[oh*51 + ow0 + t]        = fmaxf(acc[t].x, 0.f);
            s_c[1275 + oh*51 + ow0 + t] = fmaxf(acc[t].y, 0.f);
        }
    }
    __syncthreads();
    for (int q = threadIdx.x; q < 2*16*29; q += 448) {
        int u = q / 464, rc = q % 464, r = rc / 29, cl = rc % 29;
        float v = 0.f;
        if (r >= 2 && r < 14 && cl >= 2 && cl < 27) {
            const float* c = s_c + u*1275 + ((r-2)*2)*51 + (cl-2)*2;
            float m = fmaxf(fmaxf(c[0], c[1]), c[2]);
            m = fmaxf(m, fmaxf(fmaxf(c[51], c[52]), c[53]));
            v = fmaxf(m, fmaxf(fmaxf(c[102], c[103]), c[104]));
        }
        g_p1[((b*32 + co0 + u) * 16 + r) * 29 + cl] = v;
    }
}

// ---------------------------------------------------------------------------
// 3. conv2 5x5 (32->64) + relu + pool 2x2 -> padded [8][14].
//    Block=(b, 4co): 160 blocks x 240 threads. ci-split S=2; thread: 5 ow x 2 co.
__global__ void conv2_pool2(const float* __restrict__ w2, const float* __restrict__ b2) {
    extern __shared__ float sm[];
    float* s_in   = sm;            // 32*16*29 = 14848
    float* s_w    = sm + 14848;    // 32*25*4 = 3200 (co-interleaved x4)
    float* s_part = sm + 18048;    // 120*10 = 1200
    float* s_c    = sm + 19248;    // 4*300 = 1200
    int b = blockIdx.x >> 4, cog = blockIdx.x & 15;
    {
        const float4* src = (const float4*)(g_p1 + b * 14848);
        float4* dst = (float4*)s_in;
        for (int i = threadIdx.x; i < 3712; i += 240) dst[i] = src[i];
        for (int i = threadIdx.x; i < 3200; i += 240) {
            int u = i & 3, j = i >> 2;
            s_w[i] = w2[(cog*4 + u) * 800 + j];
        }
    }
    __syncthreads();
    int cihalf = threadIdx.x / 120;
    int r = threadIdx.x % 120;
    int u2 = r / 60, pos = r % 60;
    int oh = pos / 5, ow0 = (pos % 5) * 5;
    float2 acc[5] = {};
    const float2* wv = (const float2*)s_w;  // idx: (ci*25+k)*2 + u2
    int ci0 = cihalf * 16;
    for (int ci = ci0; ci < ci0 + 16; ci++) {
        const float* ip = s_in + ci*464 + oh*29 + ow0;
#pragma unroll
        for (int kh = 0; kh < 5; kh++) {
            const float* row = ip + kh*29;
            float iv[9];
#pragma unroll
            for (int m = 0; m < 9; m++) iv[m] = row[m];
#pragma unroll
            for (int kw = 0; kw < 5; kw++) {
                float2 w = wv[(ci*25 + kh*5 + kw)*2 + u2];
#pragma unroll
                for (int t = 0; t < 5; t++)
                    ffma2(acc[t], make_float2(iv[kw+t], iv[kw+t]), w);
            }
        }
    }
    if (cihalf == 1) {
#pragma unroll
        for (int t = 0; t < 5; t++) {
            s_part[r*10 + t*2    ] = acc[t].x;
            s_part[r*10 + t*2 + 1] = acc[t].y;
        }
    }
    __syncthreads();
    if (cihalf == 0) {
        int co0 = cog*4 + u2*2;
        float bx = b2[co0], by = b2[co0+1];
#pragma unroll
        for (int t = 0; t < 5; t++) {
            float vx = acc[t].x + s_part[r*10 + t*2]     + bx;
            float vy = acc[t].y + s_part[r*10 + t*2 + 1] + by;
            s_c[(u2*2  )*300 + oh*25 + ow0 + t] = fmaxf(vx, 0.f);
            s_c[(u2*2+1)*300 + oh*25 + ow0 + t] = fmaxf(vy, 0.f);
        }
    }
    __syncthreads();
    for (int q = threadIdx.x; q < 4*8*14; q += 240) {
        int u = q / 112, rc = q % 112, rr = rc / 14, cl = rc % 14;
        float v = 0.f;
        if (rr >= 1 && rr < 7 && cl >= 1 && cl < 13) {
            const float* c = s_c + u*300 + ((rr-1)*2)*25 + (cl-1)*2;
            v = fmaxf(fmaxf(c[0], c[1]), fmaxf(c[25], c[26]));
        }
        g_p2[((b*64 + cog*4 + u) * 8 + rr) * 14 + cl] = v;
    }
}

// ---------------------------------------------------------------------------
// 4. conv3 3x3 (64->128) + relu + pool 2x2 + global-avg.
//    Block=(b, 4co): 320 blocks x 288 threads. ci-split S=4; thread: 2 ow x 2 co.
__global__ void conv3_gap(const float* __restrict__ w3, const float* __restrict__ b3) {
    extern __shared__ float sm[];
    float* s_in   = sm;            // 64*8*14 = 7168
    float* s_w    = sm + 7168;     // 64*9*4 = 2304 (co-interleaved x4)
    float* s_part = sm + 9472;     // 4*288 = 1152
    float* s_c    = sm + 10624;    // 4*72 = 288
    float* s_p    = sm + 10912;    // 72
    int b = blockIdx.x >> 5, cog = blockIdx.x & 31;
    {
        const float4* src = (const float4*)(g_p2 + b * 7168);
        float4* dst = (float4*)s_in;
        for (int i = threadIdx.x; i < 1792; i += 288) dst[i] = src[i];
        for (int i = threadIdx.x; i < 2304; i += 288) {
            int u = i & 3, j = i >> 2;
            s_w[i] = w3[(cog*4 + u) * 576 + j];
        }
    }
    __syncthreads();
    int ciq = threadIdx.x / 72;
    int r = threadIdx.x % 72;
    int u2 = r / 36, pos = r % 36;
    int oh = pos / 6, ow0 = (pos % 6) * 2;
    float2 a0 = {}, a1 = {};
    const float2* wv = (const float2*)s_w;  // idx: (ci*9+k)*2 + u2
    const float2* iv2 = (const float2*)s_in;
    int ci0 = ciq * 16;
    for (int ci = ci0; ci < ci0 + 16; ci++) {
        int base = ci*112 + oh*14 + ow0;     // even
#pragma unroll
        for (int kh = 0; kh < 3; kh++) {
            int bi = (base + kh*14) >> 1;
            float2 p0 = iv2[bi], p1 = iv2[bi+1];
            float iv[4] = {p0.x, p0.y, p1.x, p1.y};
#pragma unroll
            for (int kw = 0; kw < 3; kw++) {
                float2 w = wv[(ci*9 + kh*3 + kw)*2 + u2];
                ffma2(a0, make_float2(iv[kw  ], iv[kw  ]), w);
                ffma2(a1, make_float2(iv[kw+1], iv[kw+1]), w);
            }
        }
    }
    s_part[ciq*288 + r*4 + 0] = a0.x;
    s_part[ciq*288 + r*4 + 1] = a0.y;
    s_part[ciq*288 + r*4 + 2] = a1.x;
    s_part[ciq*288 + r*4 + 3] = a1.y;
    __syncthreads();
    {
        int t = threadIdx.x;             // 0..287 -> one output each
        int rr = t / 4, j = t % 4;
        int uu = rr / 36, pp = rr % 36;
        int ooh = pp / 6, oow = (pp % 6) * 2 + (j >> 1);
        int co_l = uu*2 + (j & 1);
        float s = s_part[t] + s_part[288 + t] + s_part[576 + t] + s_part[864 + t];
        s += b3[cog*4 + co_l];
        s_c[co_l*72 + ooh*12 + oow] = fmaxf(s, 0.f);
    }
    __syncthreads();
    if (threadIdx.x < 72) {
        int co_l = threadIdx.x / 18, cell = threadIdx.x % 18;
        int ph = cell / 6, pw = cell % 6;
        const float* c = s_c + co_l*72 + (ph*2)*12 + pw*2;
        s_p[threadIdx.x] = fmaxf(fmaxf(c[0], c[1]), fmaxf(c[12], c[13]));
    }
    __syncthreads();
    if (threadIdx.x < 4) {
        float s = 0.f;
#pragma unroll
        for (int i = 0; i < 18; i++) s += s_p[threadIdx.x*18 + i];
        g_gap[b*128 + cog*4 + threadIdx.x] = s * (1.0f/18.0f);
    }
}

// ---------------------------------------------------------------------------
// 5. fc1(128->128)+relu, fc2(128->5). One block per batch row.
__global__ void fc_fused(const float* __restrict__ wl1, const float* __restrict__ bl1,
                         const float* __restrict__ wl2, const float* __restrict__ bl2,
                         float* __restrict__ out) {
    __shared__ float s_g[128];
    __shared__ float s_h[128];
    int b = blockIdx.x;
    int t = threadIdx.x;
    s_g[t] = g_gap[b*128 + t];
    __syncthreads();
    float s = bl1[t];
    const float* wr = wl1 + t*128;
#pragma unroll 8
    for (int i = 0; i < 128; i++) s += s_g[i] * wr[i];
    s_h[t] = fmaxf(s, 0.f);
    __syncthreads();
    if (t < 5) {
        float o = bl2[t];
        const float* wr2 = wl2 + t*128;
#pragma unroll 8
        for (int i = 0; i < 128; i++) o += s_h[i] * wr2[i];
        out[b*5 + t] = o;
    }
}

extern "C" void kernel_launch(void* const* d_in, const int* in_sizes, int n_in,
                              void* d_out, int out_size) {
    const int*   x   = (const int*)  d_in[0];
    const float* w1  = (const float*)d_in[1];
    const float* b1  = (const float*)d_in[2];
    const float* w2  = (const float*)d_in[3];
    const float* b2  = (const float*)d_in[4];
    const float* w3  = (const float*)d_in[5];
    const float* b3  = (const float*)d_in[6];
    const float* wl1 = (const float*)d_in[7];
    const float* bl1 = (const float*)d_in[8];
    const float* wl2 = (const float*)d_in[9];
    const float* bl2 = (const float*)d_in[10];
    float* out = (float*)d_out;

    const int smem1 = (17976 + 296 + 2550) * 4;           // 83288 B
    const int smem2 = (14848 + 3200 + 1200 + 1200) * 4;   // 81792 B
    const int smem3 = (7168 + 2304 + 1152 + 288 + 72) * 4;// 43936 B
    cudaFuncSetAttribute(conv1_pool1, cudaFuncAttributeMaxDynamicSharedMemorySize, smem1);
    cudaFuncSetAttribute(conv2_pool2, cudaFuncAttributeMaxDynamicSharedMemorySize, smem2);
    cudaFuncSetAttribute(conv3_gap,   cudaFuncAttributeMaxDynamicSharedMemorySize, smem3);

    build_grid <<<BB*CC, 1024>>>(x);
    conv1_pool1<<<BB*16, 448, smem1>>>(w1, b1);
    conv2_pool2<<<BB*16, 240, smem2>>>(w2, b2);
    conv3_gap  <<<BB*32, 288, smem3>>>(w3, b3);
    fc_fused   <<<BB, 128>>>(wl1, bl1, wl2, bl2, out);
}